// round 8
// baseline (speedup 1.0000x reference)
#include <cuda_runtime.h>

#define B_    64
#define S_    512
#define DIN_  512
#define DH_   1024
#define NCTA_RNN 128
#define RNN_THREADS 512
// smem: Wh slice (1024*32*4B=128KB) + h pairs (8*1024*8B=64KB) + reduction (16*256*8B=32KB)
#define RNN_SMEM (131072 + 65536 + 32768)

__device__ unsigned g_bars[4][32];                         // per-batch-group barrier
__device__ __align__(16) float2 g_hpair[2][32][DH_];       // ping-pong h, pre-interleaved batch pairs

// ---------------- packed f32x2 helpers (FFMA2 on sm_103a) ----------------
static __device__ __forceinline__ unsigned long long pack2(float x, float y) {
    unsigned long long r;
    asm("mov.b64 %0, {%1, %2};" : "=l"(r) : "f"(x), "f"(y));
    return r;
}
static __device__ __forceinline__ void unpack2(unsigned long long v, float &x, float &y) {
    asm("mov.b64 {%0, %1}, %2;" : "=f"(x), "=f"(y) : "l"(v));
}
static __device__ __forceinline__ unsigned long long ffma2(unsigned long long a,
                                                           unsigned long long b,
                                                           unsigned long long c) {
    unsigned long long d;
    asm("fma.rn.f32x2 %0, %1, %2, %3;" : "=l"(d) : "l"(a), "l"(b), "l"(c));
    return d;
}
static __device__ __forceinline__ unsigned long long add2(unsigned long long a,
                                                          unsigned long long b) {
    unsigned long long d;
    asm("add.rn.f32x2 %0, %1, %2;" : "=l"(d) : "l"(a), "l"(b));
    return d;
}
static __device__ __forceinline__ unsigned long long shfl_xor64(unsigned long long v, int m) {
    unsigned lo = (unsigned)v, hi = (unsigned)(v >> 32);
    lo = __shfl_xor_sync(0xffffffffu, lo, m);
    hi = __shfl_xor_sync(0xffffffffu, hi, m);
    return ((unsigned long long)hi << 32) | (unsigned long long)lo;
}

static __device__ __forceinline__ float fast_tanh(float x) {
    float xc = fminf(fmaxf(x, -15.f), 15.f);
    float e = __expf(2.f * xc);
    return 1.f - __fdividef(2.f, e + 1.f);
}

// ---------------- Kernel 1: xproj = x @ Wx + b, written into outs region ----------------
__global__ __launch_bounds__(256) void xproj_kernel(
    const float* __restrict__ X,
    const float* __restrict__ W,      // full (1536,1024); Wx = rows [0,512)
    const float* __restrict__ bias,
    float* __restrict__ C)            // (32768, 1024) = outs region
{
    __shared__ __align__(16) float As[16][132];
    __shared__ __align__(16) float Bs[16][64];

    const int tid = threadIdx.x;
    const int m0 = blockIdx.y * 128;
    const int n0 = blockIdx.x * 64;
    const int tx = tid & 15;
    const int ty = tid >> 4;
    const int ar = tid >> 2;
    const int ac = (tid & 3) << 2;
    const int br = tid >> 4;
    const int bc = (tid & 15) << 2;

    unsigned long long acc[4][4];
#pragma unroll
    for (int i = 0; i < 4; ++i)
#pragma unroll
        for (int jj = 0; jj < 4; ++jj) acc[i][jj] = 0ull;

    for (int kt = 0; kt < DIN_; kt += 16) {
        float4 a0 = *(const float4*)(X + (size_t)(m0 + ar) * DIN_ + kt + ac);
        float4 a1 = *(const float4*)(X + (size_t)(m0 + ar + 64) * DIN_ + kt + ac);
        float4 bv = *(const float4*)(W + (size_t)(kt + br) * DH_ + n0 + bc);
        As[ac + 0][ar] = a0.x; As[ac + 1][ar] = a0.y;
        As[ac + 2][ar] = a0.z; As[ac + 3][ar] = a0.w;
        As[ac + 0][ar + 64] = a1.x; As[ac + 1][ar + 64] = a1.y;
        As[ac + 2][ar + 64] = a1.z; As[ac + 3][ar + 64] = a1.w;
        *(float4*)&Bs[br][bc] = bv;
        __syncthreads();

#pragma unroll
        for (int k = 0; k < 16; ++k) {
            const unsigned long long* ap =
                (const unsigned long long*)&As[k][ty << 3];
            ulonglong2 av0 = *(const ulonglong2*)(ap);
            ulonglong2 av1 = *(const ulonglong2*)(ap + 2);
            unsigned long long a2[4] = { av0.x, av0.y, av1.x, av1.y };
            float4 bq = *(const float4*)&Bs[k][tx << 2];
            unsigned long long b2[4] = { pack2(bq.x, bq.x), pack2(bq.y, bq.y),
                                         pack2(bq.z, bq.z), pack2(bq.w, bq.w) };
#pragma unroll
            for (int i = 0; i < 4; ++i)
#pragma unroll
                for (int jj = 0; jj < 4; ++jj)
                    acc[i][jj] = ffma2(a2[i], b2[jj], acc[i][jj]);
        }
        __syncthreads();
    }

    float4 bias4 = *(const float4*)(bias + n0 + (tx << 2));
#pragma unroll
    for (int i = 0; i < 4; ++i) {
        float l0, h0, l1, h1, l2, h2, l3, h3;
        unpack2(acc[i][0], l0, h0);
        unpack2(acc[i][1], l1, h1);
        unpack2(acc[i][2], l2, h2);
        unpack2(acc[i][3], l3, h3);
        int m = m0 + (ty << 3) + (i << 1);
        float4 v0 = make_float4(l0 + bias4.x, l1 + bias4.y, l2 + bias4.z, l3 + bias4.w);
        float4 v1 = make_float4(h0 + bias4.x, h1 + bias4.y, h2 + bias4.z, h3 + bias4.w);
        *(float4*)(C + (size_t)m * DH_ + n0 + (tx << 2)) = v0;
        *(float4*)(C + (size_t)(m + 1) * DH_ + n0 + (tx << 2)) = v1;
    }
}

// ---------------- barrier reset ----------------
__global__ void reset_kernel() {
    if (threadIdx.x < 4) g_bars[threadIdx.x][0] = 0u;
}

// ---------------- Kernel 2: persistent recurrence, 512 threads ----------------
// Warp = 64-k slice. Lane = (c3 = lane>>2 in [0,8), k2 = lane&3 in [0,4)).
// Thread tile: 4 cols x 8 batch-pairs; one h LDS.64 feeds 4 FFMA2.
__global__ __launch_bounds__(RNN_THREADS, 1) void rnn_kernel(
    const float* __restrict__ h0,
    const float* __restrict__ W,      // Wh = rows [512, 1536)
    float* __restrict__ out,          // (B,S,DH): xp in, h out (in place)
    float* __restrict__ hlast)        // (B, DH)
{
    extern __shared__ unsigned char sraw[];
    float*  ws   = (float*)sraw;                           // [1024][32] Wh slice
    float2* hs   = (float2*)(sraw + 131072);               // [8 pairs][1024]
    unsigned long long* redu =
        (unsigned long long*)(sraw + 131072 + 65536);      // [16 ks][256 outs]

    const int tid = threadIdx.x;
    const int cg = blockIdx.x & 31;       // col group 0..31
    const int bg = blockIdx.x >> 5;       // batch group 0..3
    const int lane = tid & 31;
    const int wid = tid >> 5;             // warp id = k-slice 0..15
    const int k2 = lane & 3;              // k offset within macro-iter
    const int c3 = lane >> 2;             // col position 0..7
    const int c0 = c3 << 2;               // col base (4 cols per thread)

    // t==0 staging mapping
    const int half = tid >> 8;
    const int k4s = (tid & 255) << 2;

    // epilogue mapping (threads 0..255)
    const int bp2 = tid >> 5;
    const int js2 = tid & 31;
    const int jo = (cg << 5) + js2;
    const int b0 = (bg << 4) + (bp2 << 1);

    volatile unsigned* bar = &g_bars[bg][0];

    // ---- one-time: stage Wh slice (1024 x 32) into smem ----
    {
        const float* wsrc = W + (size_t)DIN_ * DH_ + (cg << 5);
        for (int idx = tid; idx < (1024 * 32) / 4; idx += RNN_THREADS) {
            int r = idx >> 3;
            int c = (idx & 7) << 2;
            float4 v = *(const float4*)(wsrc + (size_t)r * DH_ + c);
            *(float4*)(ws + r * 32 + c) = v;
        }
    }

    // ---- prefetch xp for t=0 ----
    float xpc0 = 0.f, xpc1 = 0.f;
    size_t i0 = 0, i1 = 0;
    if (tid < 256) {
        i0 = ((size_t)b0 * S_) * DH_ + jo;
        i1 = i0 + (size_t)S_ * DH_;
        xpc0 = out[i0];
        xpc1 = out[i1];
    }
    __syncthreads();

    for (int t = 0; t < S_; ++t) {
        // ---- stage h_prev into smem ----
        if (t == 0) {
            const float* base = h0 + (size_t)(bg << 4) * DH_;
#pragma unroll
            for (int q = 0; q < 4; ++q) {
                const int bp = (half << 2) + q;
                const float* r0 = base + (size_t)(bp << 1) * DH_ + k4s;
                float4 a = *(const float4*)r0;
                float4 b = *(const float4*)(r0 + DH_);
                float2* d = hs + bp * 1024 + k4s;
                d[0] = make_float2(a.x, b.x);
                d[1] = make_float2(a.y, b.y);
                d[2] = make_float2(a.z, b.z);
                d[3] = make_float2(a.w, b.w);
            }
        } else {
            const ulonglong2* src = (const ulonglong2*)g_hpair[(t - 1) & 1][bg << 3];
            ulonglong2* dst = (ulonglong2*)hs;
#pragma unroll
            for (int q = 0; q < 8; ++q)
                dst[(q << 9) + tid] = src[(q << 9) + tid];
        }

        // ---- prefetch xp for t+1 (hidden under GEMV) ----
        float xpn0 = 0.f, xpn1 = 0.f;
        if (tid < 256 && t + 1 < S_) {
            xpn0 = out[i0 + DH_];
            xpn1 = out[i1 + DH_];
        }
        __syncthreads();

        // ---- packed GEMV: thread = 4 cols x 8 bp, lane-k2 covers 4 k per iter ----
        unsigned long long acc[8][4];
#pragma unroll
        for (int bp = 0; bp < 8; ++bp)
#pragma unroll
            for (int ci = 0; ci < 4; ++ci) acc[bp][ci] = 0ull;

        {
            const int kstart = (wid << 6) + k2;    // this lane's first k
            const float* wsp = ws + kstart * 32 + c0;
            const unsigned long long* hsp =
                (const unsigned long long*)(hs + kstart);
            for (int i = 0; i < 16; ++i) {
                float4 wv = *(const float4*)(wsp + (i << 2) * 32);   // LDS.128, conflict-free
                unsigned long long w2a = pack2(wv.x, wv.x);
                unsigned long long w2b = pack2(wv.y, wv.y);
                unsigned long long w2c = pack2(wv.z, wv.z);
                unsigned long long w2d = pack2(wv.w, wv.w);
                const unsigned long long* hk = hsp + (i << 2);
#pragma unroll
                for (int bp = 0; bp < 8; ++bp) {
                    unsigned long long hv = hk[bp << 10];            // LDS.64
                    acc[bp][0] = ffma2(hv, w2a, acc[bp][0]);
                    acc[bp][1] = ffma2(hv, w2b, acc[bp][1]);
                    acc[bp][2] = ffma2(hv, w2c, acc[bp][2]);
                    acc[bp][3] = ffma2(hv, w2d, acc[bp][3]);
                }
            }
        }

        // ---- in-warp reduction over k2 (4 lanes) ----
#pragma unroll
        for (int bp = 0; bp < 8; ++bp)
#pragma unroll
            for (int ci = 0; ci < 4; ++ci) {
                unsigned long long v = acc[bp][ci];
                v = add2(v, shfl_xor64(v, 1));
                v = add2(v, shfl_xor64(v, 2));
                acc[bp][ci] = v;
            }

        // ---- cross-warp reduction through smem ----
        if (k2 == 0) {
#pragma unroll
            for (int bp = 0; bp < 8; ++bp)
#pragma unroll
                for (int ci = 0; ci < 4; ++ci)
                    redu[(wid << 8) + (bp << 5) + c0 + ci] = acc[bp][ci];
        }
        __syncthreads();

        if (tid < 256) {
            const unsigned long long* rp = redu + tid;
            float sx = 0.f, sy = 0.f;
#pragma unroll
            for (int q = 0; q < 16; ++q) {
                float x, y;
                unpack2(rp[q << 8], x, y);
                sx += x; sy += y;
            }
            float hv0 = fast_tanh(xpc0 + sx);
            float hv1 = fast_tanh(xpc1 + sy);
            out[i0] = hv0;
            out[i1] = hv1;
            g_hpair[t & 1][(bg << 3) + bp2][jo] = make_float2(hv0, hv1);
            if (t == S_ - 1) {
                hlast[(size_t)b0 * DH_ + jo] = hv0;
                hlast[(size_t)(b0 + 1) * DH_ + jo] = hv1;
            }
            i0 += DH_;
            i1 += DH_;
        }
        xpc0 = xpn0;
        xpc1 = xpn1;

        // ---- per-bg barrier: arrive + wait (32 CTAs) ----
        __syncthreads();
        if (tid == 0) {
            unsigned long long addr = (unsigned long long)bar;
            asm volatile("red.release.gpu.add.u32 [%0], 1;" :: "l"(addr) : "memory");
            const unsigned target = 32u * (unsigned)(t + 1);
            unsigned v;
            do {
                asm volatile("ld.acquire.gpu.u32 %0, [%1];" : "=r"(v) : "l"(addr) : "memory");
            } while (v < target);
        }
        __syncthreads();
    }
}

// ---------------- launch ----------------
extern "C" void kernel_launch(void* const* d_in, const int* in_sizes, int n_in,
                              void* d_out, int out_size) {
    (void)in_sizes; (void)n_in; (void)out_size;
    const float* x  = (const float*)d_in[0];
    const float* h0 = (const float*)d_in[1];
    const float* W  = (const float*)d_in[2];
    const float* b  = (const float*)d_in[3];
    float* out = (float*)d_out;                       // (B,S,DH) outs
    float* hlast = out + (size_t)B_ * S_ * DH_;       // (B,DH) h_last

    cudaFuncSetAttribute(rnn_kernel, cudaFuncAttributeMaxDynamicSharedMemorySize, RNN_SMEM);

    dim3 g1(DH_ / 64, (B_ * S_) / 128);
    xproj_kernel<<<g1, 256>>>(x, W, b, out);
    reset_kernel<<<1, 32>>>();
    rnn_kernel<<<NCTA_RNN, RNN_THREADS, RNN_SMEM>>>(h0, W, out, hlast);
}

// round 9
// speedup vs baseline: 1.3800x; 1.3800x over previous
#include <cuda_runtime.h>

#define B_    64
#define S_    512
#define DIN_  512
#define DH_   1024
#define NCTA_RNN 128
#define RNN_THREADS 512
// smem: Wh slice (1024*32*4B=128KB) + h pairs (8*1024*8B=64KB) + reduction (16*256*8B=32KB)
#define RNN_SMEM (131072 + 65536 + 32768)

__device__ unsigned g_bars[4][32];                         // per-batch-group barrier
__device__ __align__(16) float2 g_hpair[2][32][DH_];       // ping-pong h, pre-interleaved batch pairs

// ---------------- packed f32x2 helpers (FFMA2 on sm_103a) ----------------
static __device__ __forceinline__ unsigned long long pack2(float x, float y) {
    unsigned long long r;
    asm("mov.b64 %0, {%1, %2};" : "=l"(r) : "f"(x), "f"(y));
    return r;
}
static __device__ __forceinline__ void unpack2(unsigned long long v, float &x, float &y) {
    asm("mov.b64 {%0, %1}, %2;" : "=f"(x), "=f"(y) : "l"(v));
}
static __device__ __forceinline__ unsigned long long ffma2(unsigned long long a,
                                                           unsigned long long b,
                                                           unsigned long long c) {
    unsigned long long d;
    asm("fma.rn.f32x2 %0, %1, %2, %3;" : "=l"(d) : "l"(a), "l"(b), "l"(c));
    return d;
}
static __device__ __forceinline__ unsigned long long add2(unsigned long long a,
                                                          unsigned long long b) {
    unsigned long long d;
    asm("add.rn.f32x2 %0, %1, %2;" : "=l"(d) : "l"(a), "l"(b));
    return d;
}
static __device__ __forceinline__ unsigned long long shfl_xor64(unsigned long long v, int m) {
    unsigned lo = (unsigned)v, hi = (unsigned)(v >> 32);
    lo = __shfl_xor_sync(0xffffffffu, lo, m);
    hi = __shfl_xor_sync(0xffffffffu, hi, m);
    return ((unsigned long long)hi << 32) | (unsigned long long)lo;
}

static __device__ __forceinline__ float fast_tanh(float x) {
    float xc = fminf(fmaxf(x, -15.f), 15.f);
    float e = __expf(2.f * xc);
    return 1.f - __fdividef(2.f, e + 1.f);
}

// ---------------- Kernel 1: xproj = x @ Wx + b, written into outs region ----------------
__global__ __launch_bounds__(256) void xproj_kernel(
    const float* __restrict__ X,
    const float* __restrict__ W,      // full (1536,1024); Wx = rows [0,512)
    const float* __restrict__ bias,
    float* __restrict__ C)            // (32768, 1024) = outs region
{
    __shared__ __align__(16) float As[16][132];
    __shared__ __align__(16) float Bs[16][64];

    const int tid = threadIdx.x;
    const int m0 = blockIdx.y * 128;
    const int n0 = blockIdx.x * 64;
    const int tx = tid & 15;
    const int ty = tid >> 4;
    const int ar = tid >> 2;
    const int ac = (tid & 3) << 2;
    const int br = tid >> 4;
    const int bc = (tid & 15) << 2;

    unsigned long long acc[4][4];
#pragma unroll
    for (int i = 0; i < 4; ++i)
#pragma unroll
        for (int jj = 0; jj < 4; ++jj) acc[i][jj] = 0ull;

    for (int kt = 0; kt < DIN_; kt += 16) {
        float4 a0 = *(const float4*)(X + (size_t)(m0 + ar) * DIN_ + kt + ac);
        float4 a1 = *(const float4*)(X + (size_t)(m0 + ar + 64) * DIN_ + kt + ac);
        float4 bv = *(const float4*)(W + (size_t)(kt + br) * DH_ + n0 + bc);
        As[ac + 0][ar] = a0.x; As[ac + 1][ar] = a0.y;
        As[ac + 2][ar] = a0.z; As[ac + 3][ar] = a0.w;
        As[ac + 0][ar + 64] = a1.x; As[ac + 1][ar + 64] = a1.y;
        As[ac + 2][ar + 64] = a1.z; As[ac + 3][ar + 64] = a1.w;
        *(float4*)&Bs[br][bc] = bv;
        __syncthreads();

#pragma unroll
        for (int k = 0; k < 16; ++k) {
            const unsigned long long* ap =
                (const unsigned long long*)&As[k][ty << 3];
            ulonglong2 av0 = *(const ulonglong2*)(ap);
            ulonglong2 av1 = *(const ulonglong2*)(ap + 2);
            unsigned long long a2[4] = { av0.x, av0.y, av1.x, av1.y };
            float4 bq = *(const float4*)&Bs[k][tx << 2];
            unsigned long long b2[4] = { pack2(bq.x, bq.x), pack2(bq.y, bq.y),
                                         pack2(bq.z, bq.z), pack2(bq.w, bq.w) };
#pragma unroll
            for (int i = 0; i < 4; ++i)
#pragma unroll
                for (int jj = 0; jj < 4; ++jj)
                    acc[i][jj] = ffma2(a2[i], b2[jj], acc[i][jj]);
        }
        __syncthreads();
    }

    float4 bias4 = *(const float4*)(bias + n0 + (tx << 2));
#pragma unroll
    for (int i = 0; i < 4; ++i) {
        float l0, h0, l1, h1, l2, h2, l3, h3;
        unpack2(acc[i][0], l0, h0);
        unpack2(acc[i][1], l1, h1);
        unpack2(acc[i][2], l2, h2);
        unpack2(acc[i][3], l3, h3);
        int m = m0 + (ty << 3) + (i << 1);
        float4 v0 = make_float4(l0 + bias4.x, l1 + bias4.y, l2 + bias4.z, l3 + bias4.w);
        float4 v1 = make_float4(h0 + bias4.x, h1 + bias4.y, h2 + bias4.z, h3 + bias4.w);
        *(float4*)(C + (size_t)m * DH_ + n0 + (tx << 2)) = v0;
        *(float4*)(C + (size_t)(m + 1) * DH_ + n0 + (tx << 2)) = v1;
    }
}

// ---------------- barrier reset ----------------
__global__ void reset_kernel() {
    if (threadIdx.x < 4) g_bars[threadIdx.x][0] = 0u;
}

// ---------------- Kernel 2: persistent recurrence, 512 threads ----------------
// Warp = 64-k slice (wid 0..15). Lane = (cp = lane&15 -> cols 2cp,2cp+1; k1 = lane>>4).
// Thread tile: 2 cols x 8 batch-pairs (acc = 32 regs). One h LDS.64 feeds 2 FFMA2.
__global__ __launch_bounds__(RNN_THREADS, 1) void rnn_kernel(
    const float* __restrict__ h0,
    const float* __restrict__ W,      // Wh = rows [512, 1536)
    float* __restrict__ out,          // (B,S,DH): xp in, h out (in place)
    float* __restrict__ hlast)        // (B, DH)
{
    extern __shared__ unsigned char sraw[];
    float*  ws   = (float*)sraw;                           // [1024][32] Wh slice
    float2* hs   = (float2*)(sraw + 131072);               // [8 pairs][1024]
    unsigned long long* redu =
        (unsigned long long*)(sraw + 131072 + 65536);      // [16 ks][256 outs]

    const int tid = threadIdx.x;
    const int cg = blockIdx.x & 31;       // col group 0..31
    const int bg = blockIdx.x >> 5;       // batch group 0..3
    const int lane = tid & 31;
    const int wid = tid >> 5;             // warp id = k-slice 0..15
    const int cp = lane & 15;             // col-pair: cols 2cp, 2cp+1
    const int k1 = lane >> 4;             // k offset 0/1
    const unsigned long long* hsu = (const unsigned long long*)hs;

    // t==0 staging mapping
    const int half = tid >> 8;
    const int k4s = (tid & 255) << 2;

    // epilogue mapping (threads 0..255)
    const int bp2 = tid >> 5;
    const int js2 = tid & 31;
    const int jo = (cg << 5) + js2;
    const int b0 = (bg << 4) + (bp2 << 1);

    volatile unsigned* bar = &g_bars[bg][0];

    // ---- one-time: stage Wh slice (1024 x 32) into smem ----
    {
        const float* wsrc = W + (size_t)DIN_ * DH_ + (cg << 5);
        for (int idx = tid; idx < (1024 * 32) / 4; idx += RNN_THREADS) {
            int r = idx >> 3;
            int c = (idx & 7) << 2;
            float4 v = *(const float4*)(wsrc + (size_t)r * DH_ + c);
            *(float4*)(ws + r * 32 + c) = v;
        }
    }

    // ---- prefetch xp for t=0 ----
    float xpc0 = 0.f, xpc1 = 0.f;
    size_t i0 = 0, i1 = 0;
    if (tid < 256) {
        i0 = ((size_t)b0 * S_) * DH_ + jo;
        i1 = i0 + (size_t)S_ * DH_;
        xpc0 = out[i0];
        xpc1 = out[i1];
    }
    __syncthreads();

    for (int t = 0; t < S_; ++t) {
        // ---- stage h_prev into smem ----
        if (t == 0) {
            const float* base = h0 + (size_t)(bg << 4) * DH_;
#pragma unroll
            for (int q = 0; q < 4; ++q) {
                const int bp = (half << 2) + q;
                const float* r0 = base + (size_t)(bp << 1) * DH_ + k4s;
                float4 a = *(const float4*)r0;
                float4 b = *(const float4*)(r0 + DH_);
                float2* d = hs + bp * 1024 + k4s;
                d[0] = make_float2(a.x, b.x);
                d[1] = make_float2(a.y, b.y);
                d[2] = make_float2(a.z, b.z);
                d[3] = make_float2(a.w, b.w);
            }
        } else {
            const ulonglong2* src = (const ulonglong2*)g_hpair[(t - 1) & 1][bg << 3];
            ulonglong2* dst = (ulonglong2*)hs;
#pragma unroll
            for (int q = 0; q < 8; ++q)
                dst[(q << 9) + tid] = src[(q << 9) + tid];
        }

        // ---- prefetch xp for t+1 (hidden under GEMV) ----
        float xpn0 = 0.f, xpn1 = 0.f;
        if (tid < 256 && t + 1 < S_) {
            xpn0 = out[i0 + DH_];
            xpn1 = out[i1 + DH_];
        }
        __syncthreads();

        // ---- packed GEMV: thread = 2 cols x 8 bp; lane k1 covers 2 k per macro-k ----
        unsigned long long acc[8][2];
#pragma unroll
        for (int bp = 0; bp < 8; ++bp) { acc[bp][0] = 0ull; acc[bp][1] = 0ull; }

        {
            const int kstart = (wid << 6) + k1;     // this lane's first k
            const float2* wsp = (const float2*)(ws + kstart * 32 + (cp << 1));
            const unsigned long long* hsp = hsu + kstart;
#pragma unroll
            for (int i = 0; i < 32; ++i) {
                float2 wv = wsp[i << 5];            // row k = kstart + 2i (32 float2 = 2 rows)
                unsigned long long w2a = pack2(wv.x, wv.x);
                unsigned long long w2b = pack2(wv.y, wv.y);
#pragma unroll
                for (int bp = 0; bp < 8; ++bp) {
                    unsigned long long hv = hsp[(bp << 10) + (i << 1)];   // LDS.64 bcast
                    acc[bp][0] = ffma2(hv, w2a, acc[bp][0]);
                    acc[bp][1] = ffma2(hv, w2b, acc[bp][1]);
                }
            }
        }

        // ---- in-warp reduction over k1 (xor 16) ----
#pragma unroll
        for (int bp = 0; bp < 8; ++bp) {
            acc[bp][0] = add2(acc[bp][0], shfl_xor64(acc[bp][0], 16));
            acc[bp][1] = add2(acc[bp][1], shfl_xor64(acc[bp][1], 16));
        }

        // ---- cross-warp reduction through smem ----
        if (k1 == 0) {
#pragma unroll
            for (int bp = 0; bp < 8; ++bp) {
                ulonglong2 v2;
                v2.x = acc[bp][0];
                v2.y = acc[bp][1];
                *(ulonglong2*)&redu[(wid << 8) + (bp << 5) + (cp << 1)] = v2;
            }
        }
        __syncthreads();

        if (tid < 256) {
            const unsigned long long* rp = redu + tid;
            float sx = 0.f, sy = 0.f;
#pragma unroll
            for (int q = 0; q < 16; ++q) {
                float x, y;
                unpack2(rp[q << 8], x, y);
                sx += x; sy += y;
            }
            float hv0 = fast_tanh(xpc0 + sx);
            float hv1 = fast_tanh(xpc1 + sy);
            out[i0] = hv0;
            out[i1] = hv1;
            g_hpair[t & 1][(bg << 3) + bp2][jo] = make_float2(hv0, hv1);
            if (t == S_ - 1) {
                hlast[(size_t)b0 * DH_ + jo] = hv0;
                hlast[(size_t)(b0 + 1) * DH_ + jo] = hv1;
            }
            i0 += DH_;
            i1 += DH_;
        }
        xpc0 = xpn0;
        xpc1 = xpn1;

        // ---- per-bg barrier: arrive + wait (32 CTAs) ----
        __syncthreads();
        if (tid == 0) {
            unsigned long long addr = (unsigned long long)bar;
            asm volatile("red.release.gpu.add.u32 [%0], 1;" :: "l"(addr) : "memory");
            const unsigned target = 32u * (unsigned)(t + 1);
            unsigned v;
            do {
                asm volatile("ld.acquire.gpu.u32 %0, [%1];" : "=r"(v) : "l"(addr) : "memory");
            } while (v < target);
        }
        __syncthreads();
    }
}

// ---------------- launch ----------------
extern "C" void kernel_launch(void* const* d_in, const int* in_sizes, int n_in,
                              void* d_out, int out_size) {
    (void)in_sizes; (void)n_in; (void)out_size;
    const float* x  = (const float*)d_in[0];
    const float* h0 = (const float*)d_in[1];
    const float* W  = (const float*)d_in[2];
    const float* b  = (const float*)d_in[3];
    float* out = (float*)d_out;                       // (B,S,DH) outs
    float* hlast = out + (size_t)B_ * S_ * DH_;       // (B,DH) h_last

    cudaFuncSetAttribute(rnn_kernel, cudaFuncAttributeMaxDynamicSharedMemorySize, RNN_SMEM);

    dim3 g1(DH_ / 64, (B_ * S_) / 128);
    xproj_kernel<<<g1, 256>>>(x, W, b, out);
    reset_kernel<<<1, 32>>>();
    rnn_kernel<<<NCTA_RNN, RNN_THREADS, RNN_SMEM>>>(h0, W, out, hlast);
}

// round 10
// speedup vs baseline: 1.4368x; 1.0412x over previous
#include <cuda_runtime.h>

#define B_    64
#define S_    512
#define DIN_  512
#define DH_   1024
#define NCTA_RNN 128
#define RNN_THREADS 512
// smem: Wh slice (128KB) + h pairs (64KB) + reduction (32KB) + mbarrier (64B)
#define RNN_SMEM (131072 + 65536 + 32768 + 64)

__device__ unsigned g_bars[4][32];                         // per-batch-group barrier
__device__ __align__(16) float2 g_hpair[2][32][DH_];       // ping-pong h, pre-interleaved batch pairs

// ---------------- packed f32x2 helpers (FFMA2 on sm_103a) ----------------
static __device__ __forceinline__ unsigned long long pack2(float x, float y) {
    unsigned long long r;
    asm("mov.b64 %0, {%1, %2};" : "=l"(r) : "f"(x), "f"(y));
    return r;
}
static __device__ __forceinline__ void unpack2(unsigned long long v, float &x, float &y) {
    asm("mov.b64 {%0, %1}, %2;" : "=f"(x), "=f"(y) : "l"(v));
}
static __device__ __forceinline__ unsigned long long ffma2(unsigned long long a,
                                                           unsigned long long b,
                                                           unsigned long long c) {
    unsigned long long d;
    asm("fma.rn.f32x2 %0, %1, %2, %3;" : "=l"(d) : "l"(a), "l"(b), "l"(c));
    return d;
}
static __device__ __forceinline__ unsigned long long add2(unsigned long long a,
                                                          unsigned long long b) {
    unsigned long long d;
    asm("add.rn.f32x2 %0, %1, %2;" : "=l"(d) : "l"(a), "l"(b));
    return d;
}
static __device__ __forceinline__ unsigned long long shfl_xor64(unsigned long long v, int m) {
    unsigned lo = (unsigned)v, hi = (unsigned)(v >> 32);
    lo = __shfl_xor_sync(0xffffffffu, lo, m);
    hi = __shfl_xor_sync(0xffffffffu, hi, m);
    return ((unsigned long long)hi << 32) | (unsigned long long)lo;
}

static __device__ __forceinline__ float fast_tanh(float x) {
    float xc = fminf(fmaxf(x, -15.f), 15.f);
    float e = __expf(2.f * xc);
    return 1.f - __fdividef(2.f, e + 1.f);
}

static __device__ __forceinline__ unsigned smem_u32(const void* p) {
    unsigned r;
    asm("{ .reg .u64 t; cvta.to.shared.u64 t, %1; cvt.u32.u64 %0, t; }" : "=r"(r) : "l"(p));
    return r;
}

// ---------------- Kernel 1: xproj = x @ Wx + b, written into outs region ----------------
__global__ __launch_bounds__(256) void xproj_kernel(
    const float* __restrict__ X,
    const float* __restrict__ W,      // full (1536,1024); Wx = rows [0,512)
    const float* __restrict__ bias,
    float* __restrict__ C)            // (32768, 1024) = outs region
{
    __shared__ __align__(16) float As[16][132];
    __shared__ __align__(16) float Bs[16][64];

    const int tid = threadIdx.x;
    const int m0 = blockIdx.y * 128;
    const int n0 = blockIdx.x * 64;
    const int tx = tid & 15;
    const int ty = tid >> 4;
    const int ar = tid >> 2;
    const int ac = (tid & 3) << 2;
    const int br = tid >> 4;
    const int bc = (tid & 15) << 2;

    unsigned long long acc[4][4];
#pragma unroll
    for (int i = 0; i < 4; ++i)
#pragma unroll
        for (int jj = 0; jj < 4; ++jj) acc[i][jj] = 0ull;

    for (int kt = 0; kt < DIN_; kt += 16) {
        float4 a0 = *(const float4*)(X + (size_t)(m0 + ar) * DIN_ + kt + ac);
        float4 a1 = *(const float4*)(X + (size_t)(m0 + ar + 64) * DIN_ + kt + ac);
        float4 bv = *(const float4*)(W + (size_t)(kt + br) * DH_ + n0 + bc);
        As[ac + 0][ar] = a0.x; As[ac + 1][ar] = a0.y;
        As[ac + 2][ar] = a0.z; As[ac + 3][ar] = a0.w;
        As[ac + 0][ar + 64] = a1.x; As[ac + 1][ar + 64] = a1.y;
        As[ac + 2][ar + 64] = a1.z; As[ac + 3][ar + 64] = a1.w;
        *(float4*)&Bs[br][bc] = bv;
        __syncthreads();

#pragma unroll
        for (int k = 0; k < 16; ++k) {
            const unsigned long long* ap =
                (const unsigned long long*)&As[k][ty << 3];
            ulonglong2 av0 = *(const ulonglong2*)(ap);
            ulonglong2 av1 = *(const ulonglong2*)(ap + 2);
            unsigned long long a2[4] = { av0.x, av0.y, av1.x, av1.y };
            float4 bq = *(const float4*)&Bs[k][tx << 2];
            unsigned long long b2[4] = { pack2(bq.x, bq.x), pack2(bq.y, bq.y),
                                         pack2(bq.z, bq.z), pack2(bq.w, bq.w) };
#pragma unroll
            for (int i = 0; i < 4; ++i)
#pragma unroll
                for (int jj = 0; jj < 4; ++jj)
                    acc[i][jj] = ffma2(a2[i], b2[jj], acc[i][jj]);
        }
        __syncthreads();
    }

    float4 bias4 = *(const float4*)(bias + n0 + (tx << 2));
#pragma unroll
    for (int i = 0; i < 4; ++i) {
        float l0, h0, l1, h1, l2, h2, l3, h3;
        unpack2(acc[i][0], l0, h0);
        unpack2(acc[i][1], l1, h1);
        unpack2(acc[i][2], l2, h2);
        unpack2(acc[i][3], l3, h3);
        int m = m0 + (ty << 3) + (i << 1);
        float4 v0 = make_float4(l0 + bias4.x, l1 + bias4.y, l2 + bias4.z, l3 + bias4.w);
        float4 v1 = make_float4(h0 + bias4.x, h1 + bias4.y, h2 + bias4.z, h3 + bias4.w);
        *(float4*)(C + (size_t)m * DH_ + n0 + (tx << 2)) = v0;
        *(float4*)(C + (size_t)(m + 1) * DH_ + n0 + (tx << 2)) = v1;
    }
}

// ---------------- barrier reset ----------------
__global__ void reset_kernel() {
    if (threadIdx.x < 4) g_bars[threadIdx.x][0] = 0u;
}

// ---------------- Kernel 2: persistent recurrence, 512 threads ----------------
// Warp = 64-k slice (wid 0..15). Lane = (cp = lane&15 -> cols 2cp,2cp+1; k1 = lane>>4).
// Thread tile: 2 cols x 8 batch-pairs. h staged per step with ONE cp.async.bulk (TMA).
__global__ __launch_bounds__(RNN_THREADS, 1) void rnn_kernel(
    const float* __restrict__ h0,
    const float* __restrict__ W,      // Wh = rows [512, 1536)
    float* __restrict__ out,          // (B,S,DH): xp in, h out (in place)
    float* __restrict__ hlast)        // (B, DH)
{
    extern __shared__ unsigned char sraw[];
    float*  ws   = (float*)sraw;                           // [1024][32] Wh slice
    float2* hs   = (float2*)(sraw + 131072);               // [8 pairs][1024]
    unsigned long long* redu =
        (unsigned long long*)(sraw + 131072 + 65536);      // [16 ks][256 outs]
    unsigned long long* mbar =
        (unsigned long long*)(sraw + 131072 + 65536 + 32768);

    const int tid = threadIdx.x;
    const int cg = blockIdx.x & 31;       // col group 0..31
    const int bg = blockIdx.x >> 5;       // batch group 0..3
    const int lane = tid & 31;
    const int wid = tid >> 5;             // warp id = k-slice 0..15
    const int cp = lane & 15;             // col-pair: cols 2cp, 2cp+1
    const int k1 = lane >> 4;             // k offset 0/1
    const unsigned long long* hsu = (const unsigned long long*)hs;

    const unsigned hs_u32 = smem_u32(hs);
    const unsigned mbar_u32 = smem_u32(mbar);

    // t==0 staging mapping
    const int half = tid >> 8;
    const int k4s = (tid & 255) << 2;

    // epilogue mapping (threads 0..255)
    const int bp2 = tid >> 5;
    const int js2 = tid & 31;
    const int jo = (cg << 5) + js2;
    const int b0 = (bg << 4) + (bp2 << 1);

    volatile unsigned* bar = &g_bars[bg][0];

    // ---- init mbarrier ----
    if (tid == 0) {
        asm volatile("mbarrier.init.shared.b64 [%0], 1;" :: "r"(mbar_u32) : "memory");
    }

    // ---- one-time: stage Wh slice (1024 x 32) into smem ----
    {
        const float* wsrc = W + (size_t)DIN_ * DH_ + (cg << 5);
        for (int idx = tid; idx < (1024 * 32) / 4; idx += RNN_THREADS) {
            int r = idx >> 3;
            int c = (idx & 7) << 2;
            float4 v = *(const float4*)(wsrc + (size_t)r * DH_ + c);
            *(float4*)(ws + r * 32 + c) = v;
        }
    }

    // ---- prefetch xp for t=0 ----
    float xpc0 = 0.f, xpc1 = 0.f;
    size_t i0 = 0, i1 = 0;
    if (tid < 256) {
        i0 = ((size_t)b0 * S_) * DH_ + jo;
        i1 = i0 + (size_t)S_ * DH_;
        xpc0 = out[i0];
        xpc1 = out[i1];
    }
    __syncthreads();

    int ph = 0;   // mbarrier phase parity

    for (int t = 0; t < S_; ++t) {
        // ---- stage h_prev into smem ----
        if (t == 0) {
            const float* base = h0 + (size_t)(bg << 4) * DH_;
#pragma unroll
            for (int q = 0; q < 4; ++q) {
                const int bp = (half << 2) + q;
                const float* r0 = base + (size_t)(bp << 1) * DH_ + k4s;
                float4 a = *(const float4*)r0;
                float4 b = *(const float4*)(r0 + DH_);
                float2* d = hs + bp * 1024 + k4s;
                d[0] = make_float2(a.x, b.x);
                d[1] = make_float2(a.y, b.y);
                d[2] = make_float2(a.z, b.z);
                d[3] = make_float2(a.w, b.w);
            }
        } else if (tid == 0) {
            // one TMA bulk copy: 64KB contiguous g_hpair slice -> hs
            const void* src = (const void*)g_hpair[(t - 1) & 1][bg << 3];
            asm volatile("fence.proxy.async.shared::cta;" ::: "memory");
            asm volatile("mbarrier.arrive.expect_tx.shared.b64 _, [%0], %1;"
                         :: "r"(mbar_u32), "r"(65536u) : "memory");
            asm volatile("cp.async.bulk.shared::cta.global.mbarrier::complete_tx::bytes "
                         "[%0], [%1], %2, [%3];"
                         :: "r"(hs_u32), "l"(src), "r"(65536u), "r"(mbar_u32) : "memory");
        }

        // ---- prefetch xp for t+1 (overlaps TMA) ----
        float xpn0 = 0.f, xpn1 = 0.f;
        if (tid < 256 && t + 1 < S_) {
            xpn0 = out[i0 + DH_];
            xpn1 = out[i1 + DH_];
        }

        // ---- wait for h tile ----
        if (t == 0) {
            __syncthreads();
        } else {
            unsigned done;
            asm volatile(
                "{\n\t.reg .pred p;\n\t"
                "mbarrier.try_wait.parity.acquire.cta.shared::cta.b64 p, [%1], %2;\n\t"
                "selp.b32 %0, 1, 0, p;\n\t}"
                : "=r"(done) : "r"(mbar_u32), "r"((unsigned)ph) : "memory");
            if (!done) {
                asm volatile(
                    "{\n\t.reg .pred P1;\n\t"
                    "WL_%=:\n\t"
                    "mbarrier.try_wait.parity.acquire.cta.shared::cta.b64 P1, [%0], %1, 0x989680;\n\t"
                    "@P1 bra.uni WD_%=;\n\t"
                    "bra.uni WL_%=;\n\t"
                    "WD_%=:\n\t}"
                    :: "r"(mbar_u32), "r"((unsigned)ph) : "memory");
            }
            ph ^= 1;
        }

        // ---- packed GEMV: thread = 2 cols x 8 bp; lane k1 covers 2 k per macro-k ----
        unsigned long long acc[8][2];
#pragma unroll
        for (int bp = 0; bp < 8; ++bp) { acc[bp][0] = 0ull; acc[bp][1] = 0ull; }

        {
            const int kstart = (wid << 6) + k1;     // this lane's first k
            const float2* wsp = (const float2*)(ws + kstart * 32 + (cp << 1));
            const unsigned long long* hsp = hsu + kstart;
#pragma unroll
            for (int i = 0; i < 32; ++i) {
                float2 wv = wsp[i << 5];            // row k = kstart + 2i
                unsigned long long w2a = pack2(wv.x, wv.x);
                unsigned long long w2b = pack2(wv.y, wv.y);
#pragma unroll
                for (int bp = 0; bp < 8; ++bp) {
                    unsigned long long hv = hsp[(bp << 10) + (i << 1)];   // LDS.64 bcast
                    acc[bp][0] = ffma2(hv, w2a, acc[bp][0]);
                    acc[bp][1] = ffma2(hv, w2b, acc[bp][1]);
                }
            }
        }

        // ---- in-warp reduction over k1 (xor 16) ----
#pragma unroll
        for (int bp = 0; bp < 8; ++bp) {
            acc[bp][0] = add2(acc[bp][0], shfl_xor64(acc[bp][0], 16));
            acc[bp][1] = add2(acc[bp][1], shfl_xor64(acc[bp][1], 16));
        }

        // ---- cross-warp reduction through smem ----
        if (k1 == 0) {
#pragma unroll
            for (int bp = 0; bp < 8; ++bp) {
                ulonglong2 v2;
                v2.x = acc[bp][0];
                v2.y = acc[bp][1];
                *(ulonglong2*)&redu[(wid << 8) + (bp << 5) + (cp << 1)] = v2;
            }
        }
        __syncthreads();

        if (tid < 256) {
            const unsigned long long* rp = redu + tid;
            float sx = 0.f, sy = 0.f;
#pragma unroll
            for (int q = 0; q < 16; ++q) {
                float x, y;
                unpack2(rp[q << 8], x, y);
                sx += x; sy += y;
            }
            float hv0 = fast_tanh(xpc0 + sx);
            float hv1 = fast_tanh(xpc1 + sy);
            out[i0] = hv0;
            out[i1] = hv1;
            g_hpair[t & 1][(bg << 3) + bp2][jo] = make_float2(hv0, hv1);
            if (t == S_ - 1) {
                hlast[(size_t)b0 * DH_ + jo] = hv0;
                hlast[(size_t)(b0 + 1) * DH_ + jo] = hv1;
            }
            i0 += DH_;
            i1 += DH_;
        }
        xpc0 = xpn0;
        xpc1 = xpn1;

        // ---- per-bg barrier: arrive + wait (32 CTAs) ----
        __syncthreads();
        if (tid == 0) {
            unsigned long long addr = (unsigned long long)bar;
            asm volatile("red.release.gpu.add.u32 [%0], 1;" :: "l"(addr) : "memory");
            const unsigned target = 32u * (unsigned)(t + 1);
            unsigned v;
            do {
                asm volatile("ld.acquire.gpu.u32 %0, [%1];" : "=r"(v) : "l"(addr) : "memory");
            } while (v < target);
        }
        __syncthreads();
    }
}

// ---------------- launch ----------------
extern "C" void kernel_launch(void* const* d_in, const int* in_sizes, int n_in,
                              void* d_out, int out_size) {
    (void)in_sizes; (void)n_in; (void)out_size;
    const float* x  = (const float*)d_in[0];
    const float* h0 = (const float*)d_in[1];
    const float* W  = (const float*)d_in[2];
    const float* b  = (const float*)d_in[3];
    float* out = (float*)d_out;                       // (B,S,DH) outs
    float* hlast = out + (size_t)B_ * S_ * DH_;       // (B,DH) h_last

    cudaFuncSetAttribute(rnn_kernel, cudaFuncAttributeMaxDynamicSharedMemorySize, RNN_SMEM);

    dim3 g1(DH_ / 64, (B_ * S_) / 128);
    xproj_kernel<<<g1, 256>>>(x, W, b, out);
    reset_kernel<<<1, 32>>>();
    rnn_kernel<<<NCTA_RNN, RNN_THREADS, RNN_SMEM>>>(h0, W, out, hlast);
}